// round 1
// baseline (speedup 1.0000x reference)
#include <cuda_runtime.h>

#define B_DIM 2
#define E_DIM 1024
#define C_DIM 128
#define R_REL 32

// 8 MB scratch for the Gram matrices G[b,s,o] (B*E*E floats).
// __device__ global array: allowed (no runtime allocation).
__device__ float g_G[(size_t)B_DIM * E_DIM * E_DIM];

// ---------------------------------------------------------------------------
// Kernel 1: G[b] = X[b] @ X[b]^T   (E x E, K = C = 128)
// 64x64 output tile per block, 256 threads, 4x4 per-thread register tile.
// K staged through shared memory in chunks of 32 (padded to kill conflicts).
// ---------------------------------------------------------------------------
__global__ __launch_bounds__(256) void gram_kernel(const float* __restrict__ x) {
    const int b    = blockIdx.z;
    const float* X = x + (size_t)b * E_DIM * C_DIM;
    float* Gb      = g_G + (size_t)b * E_DIM * E_DIM;

    const int row0 = blockIdx.y * 64;
    const int col0 = blockIdx.x * 64;
    const int tid  = threadIdx.x;
    const int tx   = tid & 15;   // 0..15 -> 4 cols each
    const int ty   = tid >> 4;   // 0..15 -> 4 rows each

    __shared__ float As[64][33];
    __shared__ float Bs[64][33];

    float acc[4][4] = {};

    for (int kk = 0; kk < C_DIM; kk += 32) {
        // 256 threads load 2 x (64x32) = 2 x 2048 floats, 8 each per tile.
        #pragma unroll
        for (int i = 0; i < 8; i++) {
            int idx = tid + i * 256;
            int rr  = idx >> 5;   // 0..63
            int k   = idx & 31;   // 0..31
            As[rr][k] = X[(size_t)(row0 + rr) * C_DIM + kk + k];
            Bs[rr][k] = X[(size_t)(col0 + rr) * C_DIM + kk + k];
        }
        __syncthreads();

        #pragma unroll
        for (int k = 0; k < 32; k++) {
            float a[4], bv[4];
            #pragma unroll
            for (int i = 0; i < 4; i++) a[i]  = As[ty * 4 + i][k];
            #pragma unroll
            for (int j = 0; j < 4; j++) bv[j] = Bs[tx * 4 + j][k];
            #pragma unroll
            for (int i = 0; i < 4; i++)
                #pragma unroll
                for (int j = 0; j < 4; j++)
                    acc[i][j] = fmaf(a[i], bv[j], acc[i][j]);
        }
        __syncthreads();
    }

    #pragma unroll
    for (int i = 0; i < 4; i++) {
        #pragma unroll
        for (int j = 0; j < 4; j++) {
            Gb[(size_t)(row0 + ty * 4 + i) * E_DIM + (col0 + tx * 4 + j)] = acc[i][j];
        }
    }
}

// ---------------------------------------------------------------------------
// Kernel 2: out[b,s,r,o] = G[b,s,o] * R[r,s,o]
// One block per (s,r) pair; 256 threads, each handling one float4 of o.
// R row loaded once (streaming), reused for both batches -> halves R traffic.
// G rows come from L2 (8 MB, fully resident). Output streamed with __stcs.
// ---------------------------------------------------------------------------
__global__ __launch_bounds__(256) void scale_kernel(const float4* __restrict__ Rrel,
                                                    float4* __restrict__ out) {
    const int E4 = E_DIM / 4;                   // 256 float4 per row
    const int sr = blockIdx.x;
    const int s  = sr >> 5;                     // / R_REL
    const int r  = sr & (R_REL - 1);
    const int t  = threadIdx.x;                 // 0..255

    const float4* G = (const float4*)g_G;

    // R[r,s,:] — read exactly once across the whole kernel, stream it.
    float4 rv = __ldcs(&Rrel[((size_t)r * E_DIM + s) * E4 + t]);

    // G[0,s,:] and G[1,s,:] — reused 32x across r, keep cacheable.
    float4 g0 = __ldg(&G[(size_t)s * E4 + t]);
    float4 g1 = __ldg(&G[(size_t)E_DIM * E4 + (size_t)s * E4 + t]);

    float4 o0, o1;
    o0.x = g0.x * rv.x;  o0.y = g0.y * rv.y;  o0.z = g0.z * rv.z;  o0.w = g0.w * rv.w;
    o1.x = g1.x * rv.x;  o1.y = g1.y * rv.y;  o1.z = g1.z * rv.z;  o1.w = g1.w * rv.w;

    // out[b,s,r,o]: index = ((b*E + s)*R_REL + r)*E + o
    size_t base0 = (((size_t)0 * E_DIM + s) * R_REL + r) * (size_t)E4 + t;
    size_t base1 = (((size_t)1 * E_DIM + s) * R_REL + r) * (size_t)E4 + t;
    __stcs(&out[base0], o0);
    __stcs(&out[base1], o1);
}

extern "C" void kernel_launch(void* const* d_in, const int* in_sizes, int n_in,
                              void* d_out, int out_size) {
    const float* x  = (const float*)d_in[0];   // (B, E, C) fp32
    const float* Rr = (const float*)d_in[1];   // (R_REL, E, E) fp32
    float* out      = (float*)d_out;           // (B, E, R_REL, E) fp32

    dim3 ggrid(E_DIM / 64, E_DIM / 64, B_DIM); // 16 x 16 x 2
    gram_kernel<<<ggrid, 256>>>(x);

    scale_kernel<<<E_DIM * R_REL, 256>>>((const float4*)Rr, (float4*)out);

    (void)in_sizes; (void)n_in; (void)out_size;
}

// round 2
// speedup vs baseline: 1.2543x; 1.2543x over previous
#include <cuda_runtime.h>

#define B_DIM 2
#define E_DIM 1024
#define C_DIM 128
#define R_REL 32

// 8 MB scratch for the Gram matrices G[b,s,o].
__device__ float g_G[(size_t)B_DIM * E_DIM * E_DIM];

// ---------------------------------------------------------------------------
// Kernel 1: G[b] = X[b] @ X[b]^T  (1024x1024, K=128)
// 128x128 tile per block, 256 threads (16x16), 8x8 register tile per thread
// with split 4+4 row/col groups (offset 64) for conflict-free LDS.128.
// SMEM staged k-major in chunks of 16.
// ---------------------------------------------------------------------------
__global__ __launch_bounds__(256) void gram_kernel(const float* __restrict__ x) {
    const int b    = blockIdx.z;
    const float* X = x + (size_t)b * E_DIM * C_DIM;
    float* Gb      = g_G + (size_t)b * E_DIM * E_DIM;

    const int row0 = blockIdx.y * 128;
    const int col0 = blockIdx.x * 128;
    const int tid  = threadIdx.x;
    const int tx   = tid & 15;   // col group: cols tx*4..+3 and 64+tx*4..+3
    const int ty   = tid >> 4;   // row group: rows ty*4..+3 and 64+ty*4..+3

    __shared__ float As[16][132];   // k-major: As[k][row]
    __shared__ float Bs[16][132];   // k-major: Bs[k][col]

    float acc[8][8];
    #pragma unroll
    for (int i = 0; i < 8; i++)
        #pragma unroll
        for (int j = 0; j < 8; j++) acc[i][j] = 0.f;

    for (int kk = 0; kk < C_DIM; kk += 16) {
        // Load A/B tiles: 128 rows x 16 k = 512 float4 each; 2 per thread each.
        #pragma unroll
        for (int i = 0; i < 2; i++) {
            int flat = tid + i * 256;        // 0..511
            int rr   = flat >> 2;            // 0..127
            int kq   = (flat & 3) * 4;       // 0,4,8,12
            float4 av = *(const float4*)&X[(size_t)(row0 + rr) * C_DIM + kk + kq];
            float4 bv = *(const float4*)&X[(size_t)(col0 + rr) * C_DIM + kk + kq];
            As[kq + 0][rr] = av.x; As[kq + 1][rr] = av.y;
            As[kq + 2][rr] = av.z; As[kq + 3][rr] = av.w;
            Bs[kq + 0][rr] = bv.x; Bs[kq + 1][rr] = bv.y;
            Bs[kq + 2][rr] = bv.z; Bs[kq + 3][rr] = bv.w;
        }
        __syncthreads();

        #pragma unroll
        for (int k = 0; k < 16; k++) {
            float4 a0 = *(const float4*)&As[k][ty * 4];
            float4 a1 = *(const float4*)&As[k][64 + ty * 4];
            float4 b0 = *(const float4*)&Bs[k][tx * 4];
            float4 b1 = *(const float4*)&Bs[k][64 + tx * 4];
            float a[8] = {a0.x, a0.y, a0.z, a0.w, a1.x, a1.y, a1.z, a1.w};
            float bb[8] = {b0.x, b0.y, b0.z, b0.w, b1.x, b1.y, b1.z, b1.w};
            #pragma unroll
            for (int i = 0; i < 8; i++)
                #pragma unroll
                for (int j = 0; j < 8; j++)
                    acc[i][j] = fmaf(a[i], bb[j], acc[i][j]);
        }
        __syncthreads();
    }

    // Store: rows {ty*4+i, 64+ty*4+i}, cols {tx*4.., 64+tx*4..} as float4.
    #pragma unroll
    for (int ig = 0; ig < 2; ig++) {
        #pragma unroll
        for (int i = 0; i < 4; i++) {
            int row = row0 + ig * 64 + ty * 4 + i;
            float* dst = &Gb[(size_t)row * E_DIM + col0];
            float4 v0 = make_float4(acc[ig*4+i][0], acc[ig*4+i][1], acc[ig*4+i][2], acc[ig*4+i][3]);
            float4 v1 = make_float4(acc[ig*4+i][4], acc[ig*4+i][5], acc[ig*4+i][6], acc[ig*4+i][7]);
            *(float4*)&dst[tx * 4]      = v0;
            *(float4*)&dst[64 + tx * 4] = v1;
        }
    }
}

// ---------------------------------------------------------------------------
// Kernel 2: out[b,s,r,o] = G[b,s,o] * R[r,s,o]
// One block per (s, 8-r chunk); 256 threads, one float4 of o each.
// G rows live in registers across the whole r loop (8x fewer L2 G reads).
// R streamed with __ldcs (read-once), out streamed with __stcs.
// ---------------------------------------------------------------------------
#define RCHUNK 8

__global__ __launch_bounds__(256) void scale_kernel(const float4* __restrict__ Rrel,
                                                    float4* __restrict__ out) {
    const int E4  = E_DIM / 4;                 // 256 float4 per row
    const int bid = blockIdx.x;
    const int s   = bid >> 2;                  // / (R_REL/RCHUNK)
    const int rc  = (bid & 3) * RCHUNK;
    const int t   = threadIdx.x;               // 0..255

    const float4* G = (const float4*)g_G;
    float4 g0 = __ldg(&G[(size_t)s * E4 + t]);
    float4 g1 = __ldg(&G[((size_t)E_DIM + s) * E4 + t]);

    #pragma unroll
    for (int rr = 0; rr < RCHUNK; rr++) {
        const int r = rc + rr;
        float4 rv = __ldcs(&Rrel[((size_t)r * E_DIM + s) * E4 + t]);

        float4 o0, o1;
        o0.x = g0.x * rv.x;  o0.y = g0.y * rv.y;  o0.z = g0.z * rv.z;  o0.w = g0.w * rv.w;
        o1.x = g1.x * rv.x;  o1.y = g1.y * rv.y;  o1.z = g1.z * rv.z;  o1.w = g1.w * rv.w;

        size_t base0 = (((size_t)s) * R_REL + r) * (size_t)E4 + t;
        size_t base1 = (((size_t)E_DIM + s) * R_REL + r) * (size_t)E4 + t;
        __stcs(&out[base0], o0);
        __stcs(&out[base1], o1);
    }
}

extern "C" void kernel_launch(void* const* d_in, const int* in_sizes, int n_in,
                              void* d_out, int out_size) {
    const float* x  = (const float*)d_in[0];   // (B, E, C) fp32
    const float* Rr = (const float*)d_in[1];   // (R_REL, E, E) fp32
    float* out      = (float*)d_out;           // (B, E, R_REL, E) fp32

    dim3 ggrid(E_DIM / 128, E_DIM / 128, B_DIM); // 8 x 8 x 2
    gram_kernel<<<ggrid, 256>>>(x);

    scale_kernel<<<E_DIM * (R_REL / RCHUNK), 256>>>((const float4*)Rr, (float4*)out);

    (void)in_sizes; (void)n_in; (void)out_size;
}